// round 1
// baseline (speedup 1.0000x reference)
#include <cuda_runtime.h>
#include <cuda_bf16.h>

// Problem constants (from reference): L=100, C=32, KS=3, D=3, R=1.
// Inputs (metadata order):
//   d_in[0] coords   : int32  [N, 3]
//   d_in[1] in_idx   : int32  [E]
//   d_in[2] out_idx  : int32  [E]
//   d_in[3] in_feats : float32 [N, 32]
//   d_in[4] kernel   : float32 [27, 32]
// Output: float32 [N, 32]

#define C_CH 32
#define GROUPS_PER_EDGE 8   // 32 channels / 4 (float4)

__global__ void zero_out_kernel(float4* __restrict__ out, int n4) {
    int i = blockIdx.x * blockDim.x + threadIdx.x;
    if (i < n4) out[i] = make_float4(0.f, 0.f, 0.f, 0.f);
}

__global__ __launch_bounds__(256)
void mink_depthwise_conv_kernel(const int* __restrict__ coords,
                                const int* __restrict__ in_idx,
                                const int* __restrict__ out_idx,
                                const float4* __restrict__ in_feats,   // [N, 8] float4
                                const float4* __restrict__ kern,       // [27, 8] float4
                                float4* __restrict__ out,              // [N, 8] float4
                                int E) {
    long long t = (long long)blockIdx.x * blockDim.x + threadIdx.x;
    long long e = t >> 3;          // edge index
    int g = (int)(t & 7);          // float4 group within the 32-channel row
    if (e >= E) return;

    int ii = in_idx[e];
    int oi = out_idx[e];

    // kernel offset index: ((dx+1)*3 + (dy+1))*3 + (dz+1)
    int kx = coords[3 * ii + 0] - coords[3 * oi + 0] + 1;
    int ky = coords[3 * ii + 1] - coords[3 * oi + 1] + 1;
    int kz = coords[3 * ii + 2] - coords[3 * oi + 2] + 1;
    int k1d = (kx * 3 + ky) * 3 + kz;

    float4 f = in_feats[(long long)ii * GROUPS_PER_EDGE + g];
    float4 w = kern[k1d * GROUPS_PER_EDGE + g];

    float4 v;
    v.x = f.x * w.x;
    v.y = f.y * w.y;
    v.z = f.z * w.z;
    v.w = f.w * w.w;

    atomicAdd(&out[(long long)oi * GROUPS_PER_EDGE + g], v);
}

extern "C" void kernel_launch(void* const* d_in, const int* in_sizes, int n_in,
                              void* d_out, int out_size) {
    const int*    coords   = (const int*)d_in[0];
    const int*    in_idx   = (const int*)d_in[1];
    const int*    out_idx  = (const int*)d_in[2];
    const float4* in_feats = (const float4*)d_in[3];
    const float4* kern     = (const float4*)d_in[4];
    float4*       out      = (float4*)d_out;

    int E  = in_sizes[1];
    int n4 = out_size / 4;   // out_size = N * 32 floats -> N * 8 float4

    {
        int threads = 256;
        int blocks = (n4 + threads - 1) / threads;
        zero_out_kernel<<<blocks, threads>>>(out, n4);
    }
    {
        long long total = (long long)E * GROUPS_PER_EDGE;
        int threads = 256;
        long long blocks = (total + threads - 1) / threads;
        mink_depthwise_conv_kernel<<<(unsigned)blocks, threads>>>(
            coords, in_idx, out_idx, in_feats, kern, out, E);
    }
}

// round 2
// speedup vs baseline: 1.5586x; 1.5586x over previous
#include <cuda_runtime.h>
#include <cuda_bf16.h>

// Gather formulation of the sparse depthwise 3^3 conv.
// Instead of consuming the (in_idx, out_idx) edge list with atomics, rebuild
// the dense occupancy lookup grid[cell] -> row (L^3 = 1e6 cells, 4 MB) each
// launch, then each output row gathers its <=27 neighbor contributions into
// registers and does ONE plain 128B store. No atomics, no zero-init pass.
//
// Inputs (metadata order):
//   d_in[0] coords   : int32  [N, 3]     (values in [0, 100))
//   d_in[1] in_idx   : int32  [E]        (unused)
//   d_in[2] out_idx  : int32  [E]        (unused)
//   d_in[3] in_feats : float32 [N, 32]
//   d_in[4] kernel   : float32 [27, 32]
// Output: float32 [N, 32]

#define LGRID 100
#define NCELLS (LGRID * LGRID * LGRID)

__device__ int g_grid[NCELLS];   // cell -> row index, or -1

__global__ void grid_init_kernel() {
    int i = blockIdx.x * blockDim.x + threadIdx.x;
    if (i < NCELLS / 4)
        reinterpret_cast<int4*>(g_grid)[i] = make_int4(-1, -1, -1, -1);
}

__global__ void grid_build_kernel(const int* __restrict__ coords, int N) {
    int i = blockIdx.x * blockDim.x + threadIdx.x;
    if (i >= N) return;
    int x = coords[3 * i + 0];
    int y = coords[3 * i + 1];
    int z = coords[3 * i + 2];
    g_grid[(x * LGRID + y) * LGRID + z] = i;
}

__global__ __launch_bounds__(256)
void gather_conv_kernel(const int* __restrict__ coords,
                        const float4* __restrict__ feats,   // [N, 8] float4
                        const float4* __restrict__ kern,    // [27, 8] float4
                        float4* __restrict__ out,           // [N, 8] float4
                        int N)
{
    __shared__ float4 skern[27 * 8];
    if (threadIdx.x < 27 * 8) skern[threadIdx.x] = kern[threadIdx.x];
    __syncthreads();

    int t = blockIdx.x * blockDim.x + threadIdx.x;
    int o = t >> 3;        // output row
    int g = t & 7;         // float4 group within 32-channel row
    if (o >= N) return;

    int cx = coords[3 * o + 0];
    int cy = coords[3 * o + 1];
    int cz = coords[3 * o + 2];
    int base = (cx * LGRID + cy) * LGRID + cz;

    // All 27 neighbor probes are independent -> high MLP, no dependent gather.
    int nb[27];
#pragma unroll
    for (int dx = -1; dx <= 1; dx++) {
#pragma unroll
        for (int dy = -1; dy <= 1; dy++) {
#pragma unroll
            for (int dz = -1; dz <= 1; dz++) {
                int k = ((dx + 1) * 3 + (dy + 1)) * 3 + (dz + 1);
                bool ok = ((unsigned)(cx + dx) < LGRID) &
                          ((unsigned)(cy + dy) < LGRID) &
                          ((unsigned)(cz + dz) < LGRID);
                int cell = base + (dx * LGRID + dy) * LGRID + dz;
                nb[k] = ok ? g_grid[cell] : -1;
            }
        }
    }

    float4 acc = make_float4(0.f, 0.f, 0.f, 0.f);
#pragma unroll
    for (int k = 0; k < 27; k++) {
        int ib = nb[k];
        if (ib >= 0) {
            float4 f = feats[(long long)ib * 8 + g];
            float4 w = skern[k * 8 + g];
            acc.x = fmaf(f.x, w.x, acc.x);
            acc.y = fmaf(f.y, w.y, acc.y);
            acc.z = fmaf(f.z, w.z, acc.z);
            acc.w = fmaf(f.w, w.w, acc.w);
        }
    }

    out[(long long)o * 8 + g] = acc;
}

extern "C" void kernel_launch(void* const* d_in, const int* in_sizes, int n_in,
                              void* d_out, int out_size) {
    const int*    coords = (const int*)d_in[0];
    const float4* feats  = (const float4*)d_in[3];
    const float4* kern   = (const float4*)d_in[4];
    float4*       out    = (float4*)d_out;

    int N = out_size / 32;   // 32 channels per row

    {
        int threads = 256;
        int blocks = (NCELLS / 4 + threads - 1) / threads;
        grid_init_kernel<<<blocks, threads>>>();
    }
    {
        int threads = 256;
        int blocks = (N + threads - 1) / threads;
        grid_build_kernel<<<blocks, threads>>>(coords, N);
    }
    {
        long long total = (long long)N * 8;
        int threads = 256;
        int blocks = (int)((total + threads - 1) / threads);
        gather_conv_kernel<<<blocks, threads>>>(coords, feats, kern, out, N);
    }
}

// round 3
// speedup vs baseline: 1.5672x; 1.0055x over previous
#include <cuda_runtime.h>
#include <cuda_bf16.h>

// Gather formulation, v2:
//  - grid encodes row+1 (0 = empty) so the statically zero-initialized
//    __device__ array is already a valid empty grid; a post-gather clear
//    kernel zeroes only the N occupied cells (no 4 MB re-init).
//  - The 8 channel-threads of each output row cooperatively probe the 27
//    neighbor cells (thread g probes (dx,dy)-pair g; thread 0 also probes
//    pair 8), sharing results through shared memory. This removes the 8x
//    redundant probe loads and lets z-consecutive probes reuse sectors.
//
// Inputs (metadata order):
//   d_in[0] coords   : int32  [N, 3]   values in [0, 100)
//   d_in[1] in_idx   : int32  [E]      (unused)
//   d_in[2] out_idx  : int32  [E]      (unused)
//   d_in[3] in_feats : float32 [N, 32]
//   d_in[4] kernel   : float32 [27, 32]
// Output: float32 [N, 32]

#define LGRID 100
#define NCELLS (LGRID * LGRID * LGRID)
#define ROWS_PER_BLOCK 32
#define THREADS_PER_BLOCK 256   // 32 rows * 8 channel-groups
#define NB_STRIDE 28            // 27 padded

__device__ int g_grid[NCELLS];  // cell -> row+1, 0 = empty (zero-init = empty)

__global__ void grid_build_kernel(const int* __restrict__ coords, int N) {
    int i = blockIdx.x * blockDim.x + threadIdx.x;
    if (i >= N) return;
    int x = coords[3 * i + 0];
    int y = coords[3 * i + 1];
    int z = coords[3 * i + 2];
    g_grid[(x * LGRID + y) * LGRID + z] = i + 1;
}

__global__ void grid_clear_kernel(const int* __restrict__ coords, int N) {
    int i = blockIdx.x * blockDim.x + threadIdx.x;
    if (i >= N) return;
    int x = coords[3 * i + 0];
    int y = coords[3 * i + 1];
    int z = coords[3 * i + 2];
    g_grid[(x * LGRID + y) * LGRID + z] = 0;
}

__global__ __launch_bounds__(THREADS_PER_BLOCK)
void gather_conv_kernel(const int* __restrict__ coords,
                        const float4* __restrict__ feats,   // [N, 8] float4
                        const float4* __restrict__ kern,    // [27, 8] float4
                        float4* __restrict__ out,           // [N, 8] float4
                        int N)
{
    __shared__ float4 skern[27 * 8];
    __shared__ int snb[ROWS_PER_BLOCK * NB_STRIDE];

    int tid = threadIdx.x;
    if (tid < 27 * 8) skern[tid] = kern[tid];

    int rl = tid >> 3;   // row within block
    int g  = tid & 7;    // float4 channel group
    int o  = blockIdx.x * ROWS_PER_BLOCK + rl;
    bool rowvalid = (o < N);

    int cx = 0, cy = 0, cz = 0;
    if (rowvalid) {
        cx = coords[3 * o + 0];
        cy = coords[3 * o + 1];
        cz = coords[3 * o + 2];
    }

    // Cooperative probe: thread g handles (dx,dy)-pair g; thread 0 also pair 8.
    if (rowvalid) {
        int npairs = (g == 0) ? 2 : 1;
        for (int rep = 0; rep < npairs; rep++) {
            int p = (rep == 0) ? g : 8;
            int dx = p / 3 - 1;
            int dy = p % 3 - 1;
            int nx = cx + dx;
            int ny = cy + dy;
            bool xyok = ((unsigned)nx < LGRID) & ((unsigned)ny < LGRID);
            int base2 = (nx * LGRID + ny) * LGRID + cz;
            int r0 = 0, r1 = 0, r2 = 0;
            if (xyok) {
                if (cz - 1 >= 0)    r0 = g_grid[base2 - 1];
                r1 = g_grid[base2];
                if (cz + 1 < LGRID) r2 = g_grid[base2 + 1];
            }
            int kb = rl * NB_STRIDE + p * 3;
            snb[kb + 0] = r0;
            snb[kb + 1] = r1;
            snb[kb + 2] = r2;
        }
    }
    __syncthreads();

    if (!rowvalid) return;

    float4 acc = make_float4(0.f, 0.f, 0.f, 0.f);
#pragma unroll
    for (int k = 0; k < 27; k++) {
        int enc = snb[rl * NB_STRIDE + k];
        if (enc > 0) {
            float4 f = feats[(long long)(enc - 1) * 8 + g];
            float4 w = skern[k * 8 + g];
            acc.x = fmaf(f.x, w.x, acc.x);
            acc.y = fmaf(f.y, w.y, acc.y);
            acc.z = fmaf(f.z, w.z, acc.z);
            acc.w = fmaf(f.w, w.w, acc.w);
        }
    }

    out[(long long)o * 8 + g] = acc;
}

extern "C" void kernel_launch(void* const* d_in, const int* in_sizes, int n_in,
                              void* d_out, int out_size) {
    const int*    coords = (const int*)d_in[0];
    const float4* feats  = (const float4*)d_in[3];
    const float4* kern   = (const float4*)d_in[4];
    float4*       out    = (float4*)d_out;

    int N = out_size / 32;

    {
        int threads = 256;
        int blocks = (N + threads - 1) / threads;
        grid_build_kernel<<<blocks, threads>>>(coords, N);
    }
    {
        int blocks = (N + ROWS_PER_BLOCK - 1) / ROWS_PER_BLOCK;
        gather_conv_kernel<<<blocks, THREADS_PER_BLOCK>>>(coords, feats, kern, out, N);
    }
    {
        int threads = 256;
        int blocks = (N + threads - 1) / threads;
        grid_clear_kernel<<<blocks, threads>>>(coords, N);
    }
}